// round 5
// baseline (speedup 1.0000x reference)
#include <cuda_runtime.h>
#include <cstdint>

#define NB 64
#define LL 200
#define DD 300
#define PP 16
#define EPSV 1e-12f

#define MT 64      // i tile
#define NT 64      // j tile
#define KC 100     // k chunk (3 chunks of 100 = 300)
#define APAD 66    // float2 row stride for A (dup) tile
#define BPAD 68    // float row stride for B tile

#define SMEM_A_BYTES (DD * APAD * 8)        // 158400
#define SMEM_B_BYTES (KC * BPAD * 4)        // 27200 per buffer
#define SMEM_TOTAL   (SMEM_A_BYTES + 2 * SMEM_B_BYTES)  // 212800

__device__ float g_inv_n1[NB * LL * PP];
__device__ float g_inv_n2[NB * LL * PP];

// packed fp32x2 FMA (Blackwell)
#define FMA2(acc, a, b) \
    asm volatile("fma.rn.f32x2 %0, %1, %2, %0;" : "+l"(acc) : "l"(a), "l"(b))

// ---------------------------------------------------------------------------
// Precompute inv norms: inv_n[row][p] = rsqrt(max(sum_d s[row,d]^2 * k[p,d]^2, eps))
// grid (1600, 2), block 256.  Each block handles 8 rows; y=0 -> sent1, y=1 -> sent2.
// ---------------------------------------------------------------------------
__global__ void norms_kernel(const float* __restrict__ s1,
                             const float* __restrict__ s2,
                             const float* __restrict__ kern) {
    __shared__ float wsh[PP * DD];
    __shared__ float rsq[DD];
    const float* src = (blockIdx.y == 0) ? s1 : s2;
    float* dst       = (blockIdx.y == 0) ? g_inv_n1 : g_inv_n2;
    int tid = threadIdx.x;

    for (int e = tid; e < PP * DD; e += 256) {
        float k = kern[e];
        wsh[e] = k * k;
    }

    int row0 = blockIdx.x * 8;
    int ty = tid >> 4;   // p
    int tx = tid & 15;

    for (int r = 0; r < 8; r++) {
        int row = row0 + r;
        __syncthreads();
        for (int e = tid; e < DD; e += 256) {
            float v = src[row * DD + e];
            rsq[e] = v * v;
        }
        __syncthreads();
        float s = 0.f;
        for (int d = tx; d < DD; d += 16)
            s += rsq[d] * wsh[ty * DD + d];
        s += __shfl_xor_sync(0xffffffffu, s, 1);
        s += __shfl_xor_sync(0xffffffffu, s, 2);
        s += __shfl_xor_sync(0xffffffffu, s, 4);
        s += __shfl_xor_sync(0xffffffffu, s, 8);
        if (tx == 0)
            dst[row * PP + ty] = rsqrtf(fmaxf(s, EPSV));
    }
}

// ---------------------------------------------------------------------------
// cp.async stage of a B chunk: s2[b, j0..j0+63, kbase..kbase+99] -> Bs[dd][j]
// consecutive threads read consecutive d (coalesced global).
// ---------------------------------------------------------------------------
__device__ __forceinline__ void stageB_async(const float* __restrict__ s2,
                                             int b, int j0, int kbase,
                                             float* BsBuf, int tid) {
#pragma unroll
    for (int it = 0; it < (NT * KC) / 256; it++) {   // 25 iterations
        int e  = tid + it * 256;
        int j  = e / KC;
        int dd = e - j * KC;
        int jg = j0 + j;
        int jc = (jg < LL) ? jg : (LL - 1);
        const float* src = s2 + (size_t)(b * LL + jc) * DD + kbase + dd;
        unsigned dst = (unsigned)__cvta_generic_to_shared(BsBuf + dd * BPAD + j);
        int sz = (jg < LL) ? 4 : 0;  // OOB -> zero-fill
        asm volatile("cp.async.ca.shared.global [%0], [%1], 4, %2;\n"
                     :: "r"(dst), "l"(src), "r"(sz) : "memory");
    }
}

// ---------------------------------------------------------------------------
// Main kernel: grid (4 i-tiles, 16 p, 64 b), 256 threads.
// out[b,i,p] = max_j ( sum_d s1[i,d]*w_p[d]*s2[j,d] * inv_n2[j,p] ) * inv_n1[i,p]
// ---------------------------------------------------------------------------
__global__ void __launch_bounds__(256, 1)
mm_kernel(const float* __restrict__ s1, const float* __restrict__ s2,
          const float* __restrict__ kern, float* __restrict__ out) {
    extern __shared__ __align__(16) char smem[];
    float2* As2 = (float2*)smem;                       // [DD][APAD] duplicated (a,a)
    float*  Bs0 = (float*)(smem + SMEM_A_BYTES);       // two buffers [KC][BPAD]

    int tid = threadIdx.x;
    int tx = tid & 15;     // j group (4 j each)
    int ty = tid >> 4;     // i group (4 i each)
    int i0 = blockIdx.x * MT;
    int p  = blockIdx.y;
    int b  = blockIdx.z;

    // ---- stage A once: weighted by w = k^2, duplicated for f32x2 ----
    const float* kw = kern + p * DD;
    for (int e = tid; e < MT * DD; e += 256) {
        int i = e / DD, d = e - i * DD;
        int ig = i0 + i;
        float w = kw[d];
        float v = (ig < LL) ? s1[(size_t)(b * LL + ig) * DD + d] * (w * w) : 0.f;
        As2[d * APAD + i] = make_float2(v, v);
    }

    float rmax[4];
#pragma unroll
    for (int m = 0; m < 4; m++) rmax[m] = -3.402823466e38f;

    for (int jt = 0; jt < 4; jt++) {
        int j0 = jt * NT;
        unsigned long long acc[4][2];
#pragma unroll
        for (int m = 0; m < 4; m++) { acc[m][0] = 0ull; acc[m][1] = 0ull; }

        // prologue: chunk 0 -> buf 0
        stageB_async(s2, b, j0, 0, Bs0, tid);
        asm volatile("cp.async.commit_group;\n" ::: "memory");

        for (int c = 0; c < 3; c++) {
            if (c < 2) {
                stageB_async(s2, b, j0, (c + 1) * KC, Bs0 + ((c + 1) & 1) * (KC * BPAD), tid);
                asm volatile("cp.async.commit_group;\n" ::: "memory");
                asm volatile("cp.async.wait_group 1;\n" ::: "memory");
            } else {
                asm volatile("cp.async.wait_group 0;\n" ::: "memory");
            }
            __syncthreads();   // A staged (c==0,jt==0) + B chunk c visible

            const float2* Ab = As2 + (size_t)c * KC * APAD + 4 * ty;
            const float*  Bb = Bs0 + (c & 1) * (KC * BPAD) + 4 * tx;

#pragma unroll 5
            for (int kk = 0; kk < KC; kk++) {
                ulonglong2 a01 = *(const ulonglong2*)(Ab + kk * APAD);     // dup(i0..i1)
                ulonglong2 a23 = *(const ulonglong2*)(Ab + kk * APAD + 2); // dup(i2..i3)
                ulonglong2 bv  = *(const ulonglong2*)(Bb + kk * BPAD);     // (j0,j1),(j2,j3)
                FMA2(acc[0][0], a01.x, bv.x); FMA2(acc[0][1], a01.x, bv.y);
                FMA2(acc[1][0], a01.y, bv.x); FMA2(acc[1][1], a01.y, bv.y);
                FMA2(acc[2][0], a23.x, bv.x); FMA2(acc[2][1], a23.x, bv.y);
                FMA2(acc[3][0], a23.y, bv.x); FMA2(acc[3][1], a23.y, bv.y);
            }
            __syncthreads();   // done reading this B buffer
        }

        // ---- epilogue for this j tile: scale by inv_n2, running max ----
        int jg = j0 + 4 * tx;
        float inv[4];
        bool  val[4];
#pragma unroll
        for (int n = 0; n < 4; n++) {
            val[n] = (jg + n) < LL;
            inv[n] = val[n] ? g_inv_n2[(b * LL + jg + n) * PP + p] : 0.f;
        }
#pragma unroll
        for (int m = 0; m < 4; m++) {
            float lo0, hi0, lo1, hi1;
            asm("mov.b64 {%0,%1}, %2;" : "=f"(lo0), "=f"(hi0) : "l"(acc[m][0]));
            asm("mov.b64 {%0,%1}, %2;" : "=f"(lo1), "=f"(hi1) : "l"(acc[m][1]));
            float r = rmax[m];
            if (val[0]) r = fmaxf(r, lo0 * inv[0]);
            if (val[1]) r = fmaxf(r, hi0 * inv[1]);
            if (val[2]) r = fmaxf(r, lo1 * inv[2]);
            if (val[3]) r = fmaxf(r, hi1 * inv[3]);
            rmax[m] = r;
        }
    }

    // ---- reduce max across the 16 tx lanes (same 4 i's), scale, store ----
#pragma unroll
    for (int m = 0; m < 4; m++) {
        float r = rmax[m];
        r = fmaxf(r, __shfl_xor_sync(0xffffffffu, r, 1));
        r = fmaxf(r, __shfl_xor_sync(0xffffffffu, r, 2));
        r = fmaxf(r, __shfl_xor_sync(0xffffffffu, r, 4));
        r = fmaxf(r, __shfl_xor_sync(0xffffffffu, r, 8));
        int ig = i0 + 4 * ty + m;
        if (tx == 0 && ig < LL)
            out[(b * LL + ig) * PP + p] = r * g_inv_n1[(b * LL + ig) * PP + p];
    }
}

// ---------------------------------------------------------------------------
extern "C" void kernel_launch(void* const* d_in, const int* in_sizes, int n_in,
                              void* d_out, int out_size) {
    const float* s1   = (const float*)d_in[0];   // sent1 (64,200,300)
    const float* s2   = (const float*)d_in[1];   // sent2 (64,200,300)
    const float* kern = (const float*)d_in[2];   // kernel (16,300)
    float* out = (float*)d_out;                  // (64,200,16)

    cudaFuncSetAttribute(mm_kernel, cudaFuncAttributeMaxDynamicSharedMemorySize,
                         SMEM_TOTAL);

    norms_kernel<<<dim3(1600, 2), 256>>>(s1, s2, kern);
    mm_kernel<<<dim3(4, 16, 64), 256, SMEM_TOTAL>>>(s1, s2, kern, out);
}

// round 6
// speedup vs baseline: 1.0327x; 1.0327x over previous
#include <cuda_runtime.h>
#include <cstdint>

#define NB 64
#define LL 200
#define DD 300
#define PP 16
#define EPSV 1e-12f

#define MT 64      // i tile
#define NT 64      // j tile
#define KC 50      // k chunk (6 chunks of 50 = 300)
#define NCH 6
#define AST 68     // A row stride (floats), 4-way store conflict, 16B-aligned loads
#define BST 68     // B row stride (floats)

#define SMEM_A_FLOATS (DD * AST)          // 20400
#define SMEM_B_FLOATS (KC * BST)          // 3400 per buffer
#define SMEM_TOTAL ((SMEM_A_FLOATS + 2 * SMEM_B_FLOATS) * 4)   // 108800 B -> 2 CTAs/SM

__device__ float g_inv_n1[NB * LL * PP];
__device__ float g_inv_n2[NB * LL * PP];

// packed fp32x2 FMA (Blackwell): acc.(lo,hi) += a.(lo,hi) * b.(lo,hi)
#define FMA2(acc, a, b) \
    asm volatile("fma.rn.f32x2 %0, %1, %2, %0;" : "+l"(acc) : "l"(a), "l"(b))
// duplicate a scalar float into both f32x2 lanes
#define PACK2(d, s) \
    asm volatile("mov.b64 %0, {%1, %1};" : "=l"(d) : "f"(s))

// ---------------------------------------------------------------------------
// Precompute inv norms: inv_n[row][p] = rsqrt(max(sum_d s[row,d]^2 * k[p,d]^2, eps))
// ---------------------------------------------------------------------------
__global__ void norms_kernel(const float* __restrict__ s1,
                             const float* __restrict__ s2,
                             const float* __restrict__ kern) {
    __shared__ float wsh[PP * DD];
    __shared__ float rsq[DD];
    const float* src = (blockIdx.y == 0) ? s1 : s2;
    float* dst       = (blockIdx.y == 0) ? g_inv_n1 : g_inv_n2;
    int tid = threadIdx.x;

    for (int e = tid; e < PP * DD; e += 256) {
        float k = kern[e];
        wsh[e] = k * k;
    }

    int row0 = blockIdx.x * 8;
    int ty = tid >> 4;   // p
    int tx = tid & 15;

    for (int r = 0; r < 8; r++) {
        int row = row0 + r;
        __syncthreads();
        for (int e = tid; e < DD; e += 256) {
            float v = src[row * DD + e];
            rsq[e] = v * v;
        }
        __syncthreads();
        float s = 0.f;
        for (int d = tx; d < DD; d += 16)
            s += rsq[d] * wsh[ty * DD + d];
        s += __shfl_xor_sync(0xffffffffu, s, 1);
        s += __shfl_xor_sync(0xffffffffu, s, 2);
        s += __shfl_xor_sync(0xffffffffu, s, 4);
        s += __shfl_xor_sync(0xffffffffu, s, 8);
        if (tx == 0)
            dst[row * PP + ty] = rsqrtf(fmaxf(s, EPSV));
    }
}

// ---------------------------------------------------------------------------
// cp.async stage of a B chunk: s2[b, j0..j0+63, kbase..kbase+KC-1] -> Bs[dd][j]
// ---------------------------------------------------------------------------
__device__ __forceinline__ void stageB_async(const float* __restrict__ s2,
                                             int b, int j0, int kbase,
                                             float* BsBuf, int tid) {
#pragma unroll
    for (int it = 0; it < 13; it++) {
        int e = tid + it * 256;
        if (e < NT * KC) {
            int j  = e / KC;
            int dd = e - j * KC;
            int jg = j0 + j;
            int jc = (jg < LL) ? jg : (LL - 1);
            const float* src = s2 + (size_t)(b * LL + jc) * DD + kbase + dd;
            unsigned dst = (unsigned)__cvta_generic_to_shared(BsBuf + dd * BST + j);
            int sz = (jg < LL) ? 4 : 0;  // OOB -> zero-fill
            asm volatile("cp.async.ca.shared.global [%0], [%1], 4, %2;\n"
                         :: "r"(dst), "l"(src), "r"(sz) : "memory");
        }
    }
}

// ---------------------------------------------------------------------------
// Main kernel: grid (4 i-tiles, 16 p, 64 b), 256 threads, 2 CTAs/SM.
// out[b,i,p] = max_j ( sum_d s1[i,d]*w_p[d]^2*s2[j,d] * inv_n2[j,p] ) * inv_n1[i,p]
// f32x2 lanes carry (i, i+1); B scalars are packed in registers.
// Tail handling: jt==3 (8 valid j) uses a slim 1-j body (duplicate j across tx
// is idempotent under max); bx==3 (8 valid i) computes only on warp 0 (ty<2).
// ---------------------------------------------------------------------------
__global__ void __launch_bounds__(256, 2)
mm_kernel(const float* __restrict__ s1, const float* __restrict__ s2,
          const float* __restrict__ kern, float* __restrict__ out) {
    extern __shared__ __align__(16) float smem[];
    float* As = smem;                        // [DD][AST]
    float* Bs = smem + SMEM_A_FLOATS;        // 2 buffers [KC][BST]

    int tid = threadIdx.x;
    int tx = tid & 15;     // j group (4 j)
    int ty = tid >> 4;     // i group (4 i)
    int i0 = blockIdx.x * MT;
    int p  = blockIdx.y;
    int b  = blockIdx.z;

    // ---- stage A once, weighted by w = k^2, plain float [d][i] ----
    const float* kw = kern + p * DD;
    for (int e = tid; e < MT * DD; e += 256) {
        int i = e / DD, d = e - i * DD;
        int ig = i0 + i;
        float w = kw[d];
        float v = (ig < LL) ? s1[(size_t)(b * LL + ig) * DD + d] * (w * w) : 0.f;
        As[d * AST + i] = v;
    }

    const bool activeW = (blockIdx.x < 3) || (ty < 2);

    float rmax[4];
#pragma unroll
    for (int m = 0; m < 4; m++) rmax[m] = -3.402823466e38f;

    for (int jt = 0; jt < 4; jt++) {
        int j0 = jt * NT;
        unsigned long long acc[2][4];
#pragma unroll
        for (int pr = 0; pr < 2; pr++)
#pragma unroll
            for (int n = 0; n < 4; n++) acc[pr][n] = 0ull;

        stageB_async(s2, b, j0, 0, Bs, tid);
        asm volatile("cp.async.commit_group;\n" ::: "memory");

        for (int c = 0; c < NCH; c++) {
            if (c < NCH - 1) {
                stageB_async(s2, b, j0, (c + 1) * KC,
                             Bs + ((c + 1) & 1) * SMEM_B_FLOATS, tid);
                asm volatile("cp.async.commit_group;\n" ::: "memory");
                asm volatile("cp.async.wait_group 1;\n" ::: "memory");
            } else {
                asm volatile("cp.async.wait_group 0;\n" ::: "memory");
            }
            __syncthreads();   // A staged (first pass) + B chunk c visible

            if (activeW) {
                const float* Ap = As + (size_t)c * KC * AST + 4 * ty;
                const float* Bp = Bs + (c & 1) * SMEM_B_FLOATS;
                if (jt < 3) {
                    const float* Bpt = Bp + 4 * tx;
#pragma unroll 5
                    for (int kk = 0; kk < KC; kk++) {
                        ulonglong2 av = *(const ulonglong2*)(Ap + kk * AST); // (i0,i1),(i2,i3)
                        float4 bv = *(const float4*)(Bpt + kk * BST);
                        unsigned long long b0, b1, b2, b3;
                        PACK2(b0, bv.x); PACK2(b1, bv.y);
                        PACK2(b2, bv.z); PACK2(b3, bv.w);
                        FMA2(acc[0][0], av.x, b0); FMA2(acc[1][0], av.y, b0);
                        FMA2(acc[0][1], av.x, b1); FMA2(acc[1][1], av.y, b1);
                        FMA2(acc[0][2], av.x, b2); FMA2(acc[1][2], av.y, b2);
                        FMA2(acc[0][3], av.x, b3); FMA2(acc[1][3], av.y, b3);
                    }
                } else {
                    // slim tail: 8 valid j; each thread handles j = 192+(tx&7)
                    const float* Bpt = Bp + (tx & 7);
#pragma unroll 5
                    for (int kk = 0; kk < KC; kk++) {
                        ulonglong2 av = *(const ulonglong2*)(Ap + kk * AST);
                        unsigned long long bd;
                        PACK2(bd, Bpt[kk * BST]);
                        FMA2(acc[0][0], av.x, bd);
                        FMA2(acc[1][0], av.y, bd);
                    }
                }
            }
            __syncthreads();   // all warps done reading this B buffer
        }

        // ---- epilogue: scale by inv_n2[j], running max ----
        if (jt < 3) {
            int jg = j0 + 4 * tx;
            float inv[4];
#pragma unroll
            for (int n = 0; n < 4; n++)
                inv[n] = g_inv_n2[(b * LL + jg + n) * PP + p];
#pragma unroll
            for (int pr = 0; pr < 2; pr++) {
#pragma unroll
                for (int n = 0; n < 4; n++) {
                    float lo, hi;
                    asm("mov.b64 {%0,%1}, %2;" : "=f"(lo), "=f"(hi) : "l"(acc[pr][n]));
                    rmax[2 * pr + 0] = fmaxf(rmax[2 * pr + 0], lo * inv[n]);
                    rmax[2 * pr + 1] = fmaxf(rmax[2 * pr + 1], hi * inv[n]);
                }
            }
        } else {
            int jg = 192 + (tx & 7);     // always < 200
            float inv = g_inv_n2[(b * LL + jg) * PP + p];
#pragma unroll
            for (int pr = 0; pr < 2; pr++) {
                float lo, hi;
                asm("mov.b64 {%0,%1}, %2;" : "=f"(lo), "=f"(hi) : "l"(acc[pr][0]));
                rmax[2 * pr + 0] = fmaxf(rmax[2 * pr + 0], lo * inv);
                rmax[2 * pr + 1] = fmaxf(rmax[2 * pr + 1], hi * inv);
            }
        }
    }

    // ---- reduce max across the 16 tx lanes, scale by inv_n1, store ----
#pragma unroll
    for (int m = 0; m < 4; m++) {
        float r = rmax[m];
        r = fmaxf(r, __shfl_xor_sync(0xffffffffu, r, 1));
        r = fmaxf(r, __shfl_xor_sync(0xffffffffu, r, 2));
        r = fmaxf(r, __shfl_xor_sync(0xffffffffu, r, 4));
        r = fmaxf(r, __shfl_xor_sync(0xffffffffu, r, 8));
        int ig = i0 + 4 * ty + m;
        if (tx == 0 && ig < LL)
            out[(b * LL + ig) * PP + p] = r * g_inv_n1[(b * LL + ig) * PP + p];
    }
}

// ---------------------------------------------------------------------------
extern "C" void kernel_launch(void* const* d_in, const int* in_sizes, int n_in,
                              void* d_out, int out_size) {
    const float* s1   = (const float*)d_in[0];   // sent1 (64,200,300)
    const float* s2   = (const float*)d_in[1];   // sent2 (64,200,300)
    const float* kern = (const float*)d_in[2];   // kernel (16,300)
    float* out = (float*)d_out;                  // (64,200,16)

    cudaFuncSetAttribute(mm_kernel, cudaFuncAttributeMaxDynamicSharedMemorySize,
                         SMEM_TOTAL);

    norms_kernel<<<dim3(1600, 2), 256>>>(s1, s2, kern);
    mm_kernel<<<dim3(4, 16, 64), 256, SMEM_TOTAL>>>(s1, s2, kern, out);
}

// round 8
// speedup vs baseline: 4.4355x; 4.2949x over previous
#include <cuda_runtime.h>
#include <cuda_bf16.h>
#include <cstdint>

#define NB 64
#define LL 200
#define DD 300
#define DP 320
#define PP 16
#define EPSV 1e-12f
#define KC 64
#define NCH 5
#define NT_THREADS 416   // 13 warps

#define RSB 144          // row stride bytes (72 bf16 = 9 x 16B, conflict-free)
#define A_PLANE 29952    // 208 * 144
#define A_BUFST 59904    // hi+lo
#define B_PLANE 14976    // 104 * 144
#define B_BUFST 29952

#define SM_WSQ   0                   // 320 floats
#define SM_INV2  1280                // 208 floats
#define SM_A     2112                // 2 bufs x (hi|lo)
#define SM_B     (SM_A + 2*A_BUFST)          // 121920
#define SM_WRED  (SM_B + 2*B_BUFST)          // 181824 (13*104 floats)
#define SM_TOTAL (SM_WRED + 13*104*4)        // 187232

__device__ float g_inv_n1[NB*LL*PP];
__device__ float g_inv_n2[NB*LL*PP];
__device__ unsigned short g_s2h[(size_t)NB*LL*DP];
__device__ unsigned short g_s2l[(size_t)NB*LL*DP];

// ---------------- PTX helpers ----------------
__device__ __forceinline__ unsigned smem_u32(const void* p) {
    unsigned a;
    asm("{ .reg .u64 t; cvta.to.shared.u64 t, %1; cvt.u32.u64 %0, t; }"
        : "=r"(a) : "l"(p));
    return a;
}

#define CP16(dst, src) \
    asm volatile("cp.async.cg.shared.global [%0], [%1], 16;" \
                 :: "r"(dst), "l"(src) : "memory")
#define CP_COMMIT() asm volatile("cp.async.commit_group;" ::: "memory")
#define CP_WAIT(n)  asm volatile("cp.async.wait_group %0;" :: "n"(n) : "memory")

#define LDSM4(r, a) \
    asm volatile("ldmatrix.sync.aligned.m8n8.x4.shared.b16 {%0,%1,%2,%3}, [%4];" \
        : "=r"((r)[0]),"=r"((r)[1]),"=r"((r)[2]),"=r"((r)[3]) : "r"(a))
#define LDSM2(r, a) \
    asm volatile("ldmatrix.sync.aligned.m8n8.x2.shared.b16 {%0,%1}, [%2];" \
        : "=r"((r)[0]),"=r"((r)[1]) : "r"(a))

#define MMA(c, a, b) \
    asm volatile("mma.sync.aligned.m16n8k16.row.col.f32.bf16.bf16.f32 " \
        "{%0,%1,%2,%3}, {%4,%5,%6,%7}, {%8,%9}, {%0,%1,%2,%3};" \
        : "+f"((c)[0]),"+f"((c)[1]),"+f"((c)[2]),"+f"((c)[3]) \
        : "r"((a)[0]),"r"((a)[1]),"r"((a)[2]),"r"((a)[3]), \
          "r"((b)[0]),"r"((b)[1]))

// ---------------------------------------------------------------------------
// inv norms: inv_n[row][p] = rsqrt(max(sum_d s[row,d]^2 * k[p,d]^2, eps))
// ---------------------------------------------------------------------------
__global__ void norms_kernel(const float* __restrict__ s1,
                             const float* __restrict__ s2,
                             const float* __restrict__ kern) {
    __shared__ float wsh[PP * DD];
    __shared__ float rsq[DD];
    const float* src = (blockIdx.y == 0) ? s1 : s2;
    float* dst       = (blockIdx.y == 0) ? g_inv_n1 : g_inv_n2;
    int tid = threadIdx.x;
    for (int e = tid; e < PP * DD; e += 256) {
        float k = kern[e];
        wsh[e] = k * k;
    }
    int row0 = blockIdx.x * 8;
    int ty = tid >> 4, tx = tid & 15;
    for (int r = 0; r < 8; r++) {
        int row = row0 + r;
        __syncthreads();
        for (int e = tid; e < DD; e += 256) {
            float v = src[row * DD + e];
            rsq[e] = v * v;
        }
        __syncthreads();
        float s = 0.f;
        for (int d = tx; d < DD; d += 16)
            s += rsq[d] * wsh[ty * DD + d];
        s += __shfl_xor_sync(0xffffffffu, s, 1);
        s += __shfl_xor_sync(0xffffffffu, s, 2);
        s += __shfl_xor_sync(0xffffffffu, s, 4);
        s += __shfl_xor_sync(0xffffffffu, s, 8);
        if (tx == 0)
            dst[row * PP + ty] = rsqrtf(fmaxf(s, EPSV));
    }
}

// ---------------------------------------------------------------------------
// split s2 -> bf16 hi/lo, K padded to 320 with zeros
// ---------------------------------------------------------------------------
__global__ void split2_kernel(const float* __restrict__ s2) {
    size_t idx = (size_t)blockIdx.x * 256 + threadIdx.x;
    if (idx >= (size_t)NB * LL * DP) return;
    int d = (int)(idx % DP);
    size_t row = idx / DP;
    float v = (d < DD) ? s2[row * DD + d] : 0.f;
    __nv_bfloat16 h = __float2bfloat16(v);
    __nv_bfloat16 l = __float2bfloat16(v - __bfloat162float(h));
    g_s2h[idx] = *(unsigned short*)&h;
    g_s2l[idx] = *(unsigned short*)&l;
}

// ---------------------------------------------------------------------------
// stage A chunk (j-side = s2 split, 208 rows): cp.async 16B, rows >=200 clamp
// ---------------------------------------------------------------------------
__device__ __forceinline__ void stageA(unsigned aHb, int b, int c, int tid) {
#pragma unroll
    for (int it = 0; it < 4; it++) {
        int e = tid + it * NT_THREADS;       // 0..1663
        int r = e >> 3, sub = e & 7;
        int j = (r < LL) ? r : (LL - 1);
        size_t g = ((size_t)(b * LL + j)) * DP + c * KC + sub * 8;
        unsigned dst = aHb + r * RSB + sub * 16;
        CP16(dst, g_s2h + g);
        CP16(dst + A_PLANE, g_s2l + g);
    }
}

// ---------------------------------------------------------------------------
// stage B chunk (i-side = s1 * w^2, 104 rows, rows>=100 zero): convert in-CTA
// ---------------------------------------------------------------------------
__device__ __forceinline__ void stageB(unsigned bHb, const float* __restrict__ s1,
                                       const float* __restrict__ wsq,
                                       int b, int bx, int c, int tid) {
#pragma unroll
    for (int it = 0; it < 4; it++) {
        int e = tid + it * NT_THREADS;       // 0..1663
        int r = e >> 4, g = e & 15;
        int d = c * KC + g * 4;
        float4 v = make_float4(0.f, 0.f, 0.f, 0.f);
        if (d < DD && r < 100)
            v = *(const float4*)(s1 + ((size_t)(b * LL + bx * 100 + r)) * DD + d);
        float4 w = *(const float4*)(wsq + d);
        float a0 = v.x * w.x, a1 = v.y * w.y, a2 = v.z * w.z, a3 = v.w * w.w;
        __nv_bfloat16 h0 = __float2bfloat16(a0), h1 = __float2bfloat16(a1);
        __nv_bfloat16 h2 = __float2bfloat16(a2), h3 = __float2bfloat16(a3);
        __nv_bfloat16 l0 = __float2bfloat16(a0 - __bfloat162float(h0));
        __nv_bfloat16 l1 = __float2bfloat16(a1 - __bfloat162float(h1));
        __nv_bfloat16 l2 = __float2bfloat16(a2 - __bfloat162float(h2));
        __nv_bfloat16 l3 = __float2bfloat16(a3 - __bfloat162float(h3));
        unsigned hu0 = ((unsigned)*(unsigned short*)&h1 << 16) | *(unsigned short*)&h0;
        unsigned hu1 = ((unsigned)*(unsigned short*)&h3 << 16) | *(unsigned short*)&h2;
        unsigned lu0 = ((unsigned)*(unsigned short*)&l1 << 16) | *(unsigned short*)&l0;
        unsigned lu1 = ((unsigned)*(unsigned short*)&l3 << 16) | *(unsigned short*)&l2;
        unsigned dst = bHb + r * RSB + g * 8;
        asm volatile("st.shared.v2.b32 [%0], {%1, %2};" :: "r"(dst), "r"(hu0), "r"(hu1) : "memory");
        asm volatile("st.shared.v2.b32 [%0], {%1, %2};" :: "r"(dst + B_PLANE), "r"(lu0), "r"(lu1) : "memory");
    }
}

// ---------------------------------------------------------------------------
// Main kernel: grid (2 i-halves, 16 p, 64 b), 416 threads (13 warps).
// M = j (208 rows, 13 m16-tiles, one per warp), N = i (104, 13 n8-tiles), K = 320.
// ---------------------------------------------------------------------------
__global__ void __launch_bounds__(NT_THREADS, 1)
mm_kernel(const float* __restrict__ s1, const float* __restrict__ s2,
          const float* __restrict__ kern, float* __restrict__ out) {
    extern __shared__ __align__(16) char smem[];
    unsigned sb = smem_u32(smem);
    float* wsq   = (float*)(smem + SM_WSQ);
    float* inv2s = (float*)(smem + SM_INV2);
    float* wred  = (float*)(smem + SM_WRED);

    int tid = threadIdx.x;
    int lane = tid & 31, wid = tid >> 5;
    int bx = blockIdx.x, p = blockIdx.y, b = blockIdx.z;

    // stage w^2 (zero-padded to 320) and clamped inv_n2
    for (int e = tid; e < DP; e += NT_THREADS) {
        float k = (e < DD) ? kern[p * DD + e] : 0.f;
        wsq[e] = k * k;
    }
    for (int e = tid; e < 208; e += NT_THREADS) {
        int j = (e < LL) ? e : (LL - 1);
        inv2s[e] = g_inv_n2[(b * LL + j) * PP + p];
    }
    __syncthreads();

    float acc[13][4];
#pragma unroll
    for (int nt = 0; nt < 13; nt++)
#pragma unroll
        for (int q = 0; q < 4; q++) acc[nt][q] = 0.f;

    // per-lane ldmatrix offsets
    unsigned a_off = (unsigned)((wid * 16 + (lane & 15)) * RSB + ((lane >> 4) << 4));
    unsigned b_off4 = (unsigned)(((lane & 7) + ((lane >> 4) << 3)) * RSB + (((lane >> 3) & 1) << 4));
    unsigned b_off2 = (unsigned)((lane & 7) * RSB + (((lane >> 3) & 1) << 4));

    // prologue: chunk 0 -> buf 0
    stageA(sb + SM_A, b, 0, tid);
    stageB(sb + SM_B, s1, wsq, b, bx, 0, tid);
    CP_COMMIT();

    for (int c = 0; c < NCH; c++) {
        if (c + 1 < NCH) {
            int nb = (c + 1) & 1;
            stageA(sb + SM_A + nb * A_BUFST, b, c + 1, tid);
            stageB(sb + SM_B + nb * B_BUFST, s1, wsq, b, bx, c + 1, tid);
            CP_COMMIT();
            CP_WAIT(1);
        } else {
            CP_WAIT(0);
        }
        __syncthreads();     // chunk c fully staged (cp.async + smem stores)

        unsigned aH = sb + SM_A + (c & 1) * A_BUFST;
        unsigned bH = sb + SM_B + (c & 1) * B_BUFST;
        unsigned ah[4], al[4], bh[4], bl[4];
#pragma unroll
        for (int ks = 0; ks < 4; ks++) {
            unsigned aaddr = aH + a_off + ks * 32;
            LDSM4(ah, aaddr);
            LDSM4(al, aaddr + A_PLANE);
#pragma unroll
            for (int t2 = 0; t2 < 6; t2++) {
                int nt = t2 * 2;
                unsigned baddr = bH + b_off4 + nt * (8 * RSB) + ks * 32;
                LDSM4(bh, baddr);
                LDSM4(bl, baddr + B_PLANE);
                MMA(acc[nt], ah, bh);
                MMA(acc[nt], ah, bl);
                MMA(acc[nt], al, bh);
                MMA(acc[nt + 1], ah, bh + 2);
                MMA(acc[nt + 1], ah, bl + 2);
                MMA(acc[nt + 1], al, bh + 2);
            }
            unsigned baddr = bH + b_off2 + 12 * (8 * RSB) + ks * 32;
            LDSM2(bh, baddr);
            LDSM2(bl, baddr + B_PLANE);
            MMA(acc[12], ah, bh);
            MMA(acc[12], ah, bl);
            MMA(acc[12], al, bh);
        }
        __syncthreads();     // all warps done reading buf (c&1)
    }

    // ---- epilogue: scale by inv_n2[j], max over j ----
    float invA = inv2s[wid * 16 + (lane >> 2)];
    float invB = inv2s[wid * 16 + (lane >> 2) + 8];
#pragma unroll
    for (int nt = 0; nt < 13; nt++) {
        float v0 = fmaxf(acc[nt][0] * invA, acc[nt][2] * invB);
        float v1 = fmaxf(acc[nt][1] * invA, acc[nt][3] * invB);
        v0 = fmaxf(v0, __shfl_xor_sync(0xffffffffu, v0, 4));
        v0 = fmaxf(v0, __shfl_xor_sync(0xffffffffu, v0, 8));
        v0 = fmaxf(v0, __shfl_xor_sync(0xffffffffu, v0, 16));
        v1 = fmaxf(v1, __shfl_xor_sync(0xffffffffu, v1, 4));
        v1 = fmaxf(v1, __shfl_xor_sync(0xffffffffu, v1, 8));
        v1 = fmaxf(v1, __shfl_xor_sync(0xffffffffu, v1, 16));
        if (lane < 4) {
            wred[wid * 104 + nt * 8 + 2 * lane]     = v0;
            wred[wid * 104 + nt * 8 + 2 * lane + 1] = v1;
        }
    }
    __syncthreads();

    if (tid < 100) {
        int n = tid;
        float m = wred[n];
#pragma unroll
        for (int w = 1; w < 13; w++) m = fmaxf(m, wred[w * 104 + n]);
        int ig = bx * 100 + n;
        out[((size_t)(b * LL + ig)) * PP + p] = m * g_inv_n1[(b * LL + ig) * PP + p];
    }
}

// ---------------------------------------------------------------------------
extern "C" void kernel_launch(void* const* d_in, const int* in_sizes, int n_in,
                              void* d_out, int out_size) {
    const float* s1   = (const float*)d_in[0];   // (64,200,300)
    const float* s2   = (const float*)d_in[1];   // (64,200,300)
    const float* kern = (const float*)d_in[2];   // (16,300)
    float* out = (float*)d_out;                  // (64,200,16)

    cudaFuncSetAttribute(mm_kernel, cudaFuncAttributeMaxDynamicSharedMemorySize,
                         SM_TOTAL);

    norms_kernel<<<dim3(1600, 2), 256>>>(s1, s2, kern);
    split2_kernel<<<(int)(((size_t)NB * LL * DP + 255) / 256), 256>>>(s2);
    mm_kernel<<<dim3(2, PP, NB), NT_THREADS, SM_TOTAL>>>(s1, s2, kern, out);
}